// round 2
// baseline (speedup 1.0000x reference)
#include <cuda_runtime.h>
#include <math.h>

// Problem dims
#define BB   32      // batch
#define TL   256     // listener T
#define DL   512     // listener feature dim (== H)
#define HH   512     // hidden
#define VV   2000    // vocab
#define MM   256     // attention MLP dim
#define G4   2048    // 4*H gate rows
#define XD   2512    // V + H (decoder input)
#define CATD 1024    // [rnn_out, context]
#define NSTEP 100

// Persistent scratch (static device allocations are allowed)
__device__ float g_x[BB * XD];                 // decoder input [b][k] (raw_pred ++ context)
__device__ float g_h0[BB * HH], g_c0[BB * HH];
__device__ float g_h1[BB * HH], g_c1[BB * HH];
__device__ float g_cat[BB * CATD];             // [h1, context]
__device__ float g_parts[8 * G4 * BB];         // K-split partial sums: [slot][row][b]
__device__ float g_clisT[(size_t)BB * MM * TL];// relu(psi(listener)) transposed: [b][m][t]

__device__ __forceinline__ float sigmoidf_(float x) { return 1.f / (1.f + expf(-x)); }

// ---------------------------------------------------------------------------
// One-time init: zero LSTM states, build x0 = [onehot(0), listener[:,0,:]]
// ---------------------------------------------------------------------------
__global__ void k_init(const float* __restrict__ lis) {
    int i = blockIdx.x * blockDim.x + threadIdx.x;
    if (i < BB * XD) {
        int b = i / XD, k = i % XD;
        float v = 0.f;
        if (k == 0) v = 1.f;
        else if (k >= VV) v = lis[(size_t)b * TL * DL + (k - VV)];
        g_x[i] = v;
    }
    if (i < BB * HH) {
        g_h0[i] = 0.f; g_c0[i] = 0.f; g_h1[i] = 0.f; g_c1[i] = 0.f;
    }
}

// ---------------------------------------------------------------------------
// One-time psi: g_clisT[b][m][t] = relu(listener[b][t] . Wpsi[m] + bpsi[m])
// block: 128 thr, tile 32m x 64t, thread tile 4x4
// grid: (mB=8, tB=4, b=32)
// ---------------------------------------------------------------------------
__global__ void k_psi(const float* __restrict__ lis,
                      const float* __restrict__ Wpsi,
                      const float* __restrict__ bpsi) {
    int mb = blockIdx.x, tb = blockIdx.y, b = blockIdx.z;
    int tid = threadIdx.x;
    int mg = tid >> 4, tg = tid & 15;   // 8 m-groups x 16 t-groups
    __shared__ float Ws[32 * 33];
    __shared__ float Ls[64 * 33];
    float acc[4][4] = {};
    const float* lb = lis + (size_t)b * TL * DL;

    for (int kc = 0; kc < DL; kc += 32) {
#pragma unroll
        for (int i = 0; i < 8; i++) {           // Wpsi tile: 32 rows x 32 k
            int lin = tid + i * 128;
            int row = lin >> 5, kk = lin & 31;
            Ws[row * 33 + kk] = Wpsi[(size_t)(mb * 32 + row) * DL + kc + kk];
        }
#pragma unroll
        for (int i = 0; i < 16; i++) {          // listener tile: 64 t x 32 k
            int lin = tid + i * 128;
            int row = lin >> 5, kk = lin & 31;
            Ls[row * 33 + kk] = lb[(size_t)(tb * 64 + row) * DL + kc + kk];
        }
        __syncthreads();
#pragma unroll 8
        for (int kk = 0; kk < 32; kk++) {
            float wv[4], lv[4];
#pragma unroll
            for (int i = 0; i < 4; i++) wv[i] = Ws[(mg * 4 + i) * 33 + kk];
#pragma unroll
            for (int j = 0; j < 4; j++) lv[j] = Ls[(tg * 4 + j) * 33 + kk];
#pragma unroll
            for (int i = 0; i < 4; i++)
#pragma unroll
                for (int j = 0; j < 4; j++) acc[i][j] = fmaf(wv[i], lv[j], acc[i][j]);
        }
        __syncthreads();
    }
#pragma unroll
    for (int i = 0; i < 4; i++) {
        int m = mb * 32 + mg * 4 + i;
        float bias = bpsi[m];
#pragma unroll
        for (int j = 0; j < 4; j++) {
            int t = tb * 64 + tg * 4 + j;
            g_clisT[((size_t)b * MM + m) * TL + t] = fmaxf(acc[i][j] + bias, 0.f);
        }
    }
}

// ---------------------------------------------------------------------------
// Generic K-split GEMM partial: P[s][r][b] = sum_{k in slice s} W[r][k]*X[b][k]
// Handles two (W,X,K) pairs: blockIdx.y < S1 -> pair 1, else pair 2.
// block: 128 thr, tile 64 rows x 32 batch, thread tile 4x4.
// ---------------------------------------------------------------------------
__global__ void k_gemm(const float* __restrict__ W1, const float* __restrict__ X1, int K1, int S1,
                       const float* __restrict__ W2, const float* __restrict__ X2, int K2,
                       int Mrows, float* __restrict__ P) {
    int s = blockIdx.y;
    const float* Wp; const float* Xp; int K, Ssub, sl;
    if (s < S1) { Wp = W1; Xp = X1; K = K1; Ssub = S1; sl = s; }
    else        { Wp = W2; Xp = X2; K = K2; Ssub = gridDim.y - S1; sl = s - S1; }
    int chunk = (K + Ssub - 1) / Ssub;
    int k0 = sl * chunk;
    int k1 = min(K, k0 + chunk);

    int rBase = blockIdx.x * 64;
    int tid = threadIdx.x;
    int rowg = tid >> 3, bg = tid & 7;          // 16 row-groups x 8 b-groups
    __shared__ float Ws[64 * 33];
    __shared__ float Xs[32 * 33];
    float acc[4][4] = {};

    for (int kc = k0; kc < k1; kc += 32) {
#pragma unroll
        for (int i = 0; i < 16; i++) {          // W tile: 64 rows x 32 k
            int lin = tid + i * 128;
            int row = lin >> 5, kk = lin & 31;
            int k = kc + kk;
            int r = rBase + row;
            float v = 0.f;
            if (k < k1 && r < Mrows) v = Wp[(size_t)r * K + k];
            Ws[row * 33 + kk] = v;
        }
#pragma unroll
        for (int i = 0; i < 8; i++) {           // X tile: 32 b x 32 k
            int lin = tid + i * 128;
            int bb = lin >> 5, kk = lin & 31;
            int k = kc + kk;
            Xs[bb * 33 + kk] = (k < k1) ? Xp[(size_t)bb * K + k] : 0.f;
        }
        __syncthreads();
#pragma unroll 8
        for (int kk = 0; kk < 32; kk++) {
            float wv[4], xv[4];
#pragma unroll
            for (int i = 0; i < 4; i++) wv[i] = Ws[(rowg * 4 + i) * 33 + kk];
#pragma unroll
            for (int j = 0; j < 4; j++) xv[j] = Xs[(bg * 4 + j) * 33 + kk];
#pragma unroll
            for (int i = 0; i < 4; i++)
#pragma unroll
                for (int j = 0; j < 4; j++) acc[i][j] = fmaf(wv[i], xv[j], acc[i][j]);
        }
        __syncthreads();
    }

    float* Pout = P + (size_t)s * G4 * BB;
#pragma unroll
    for (int i = 0; i < 4; i++) {
        int r = rBase + rowg * 4 + i;
#pragma unroll
        for (int j = 0; j < 4; j++) {
            Pout[(size_t)r * BB + bg * 4 + j] = acc[i][j];
        }
    }
}

// ---------------------------------------------------------------------------
// LSTM cell: reduce K-split partials + biases, apply gates. In-place h/c.
// grid 64 x 256 -> idx = j*32 + b  (coalesced partial reads)
// ---------------------------------------------------------------------------
__global__ void k_cell(const float* __restrict__ P, int npart,
                       const float* __restrict__ bih, const float* __restrict__ bhh,
                       float* __restrict__ hbuf, float* __restrict__ cbuf,
                       float* __restrict__ hcopy) {
    int idx = blockIdx.x * blockDim.x + threadIdx.x;
    if (idx >= BB * HH) return;
    int b = idx & 31, j = idx >> 5;
    float g[4];
#pragma unroll
    for (int gi = 0; gi < 4; gi++) {
        int r = gi * HH + j;
        float v = bih[r] + bhh[r];
        for (int s = 0; s < npart; s++) v += P[((size_t)s * G4 + r) * BB + b];
        g[gi] = v;
    }
    float ig = sigmoidf_(g[0]);
    float fg = sigmoidf_(g[1]);
    float gg = tanhf(g[2]);
    float og = sigmoidf_(g[3]);
    float cp = cbuf[b * HH + j];
    float cn = fg * cp + ig * gg;
    float hn = og * tanhf(cn);
    cbuf[b * HH + j] = cn;
    hbuf[b * HH + j] = hn;
    if (hcopy) hcopy[b * CATD + j] = hn;
}

// ---------------------------------------------------------------------------
// Attention: comp_dec (from phi partials slots 0,1) -> energy -> softmax ->
// context. One block per batch. Writes attn to output and context to g_cat/g_x.
// ---------------------------------------------------------------------------
__global__ void k_attn(const float* __restrict__ lis,
                       const float* __restrict__ bphi,
                       float* __restrict__ attn_out) {
    int b = blockIdx.x, tid = threadIdx.x;    // 256 threads, tid == t == m
    __shared__ float cd[MM];
    __shared__ float av[TL];
    __shared__ float rbuf[TL];

    float v = g_parts[(size_t)(0 * G4 + tid) * BB + b]
            + g_parts[(size_t)(1 * G4 + tid) * BB + b] + bphi[tid];
    cd[tid] = fmaxf(v, 0.f);
    __syncthreads();

    const float* cl = g_clisT + (size_t)b * MM * TL + tid;
    float e = 0.f;
#pragma unroll 8
    for (int m = 0; m < MM; m++) e = fmaf(cd[m], cl[(size_t)m * TL], e);

    rbuf[tid] = e; __syncthreads();
    for (int o = 128; o > 0; o >>= 1) {
        if (tid < o) rbuf[tid] = fmaxf(rbuf[tid], rbuf[tid + o]);
        __syncthreads();
    }
    float mx = rbuf[0];
    __syncthreads();
    float p = expf(e - mx);
    rbuf[tid] = p; __syncthreads();
    for (int o = 128; o > 0; o >>= 1) {
        if (tid < o) rbuf[tid] += rbuf[tid + o];
        __syncthreads();
    }
    float a = p / rbuf[0];
    av[tid] = a;
    attn_out[b * TL + tid] = a;
    __syncthreads();

    const float* lb = lis + (size_t)b * TL * DL;
    for (int d = tid; d < DL; d += blockDim.x) {
        float c = 0.f;
        for (int t = 0; t < TL; t++) c = fmaf(av[t], lb[(size_t)t * DL + d], c);
        g_cat[b * CATD + HH + d] = c;
        g_x[b * XD + VV + d] = c;
    }
}

// ---------------------------------------------------------------------------
// Log-softmax over vocab: reduce logits partials (slots 0..3) + bc,
// write preds output and feedback into g_x[:, :V]. One block per batch.
// ---------------------------------------------------------------------------
__global__ void k_logsm(const float* __restrict__ bc, float* __restrict__ preds_out) {
    int b = blockIdx.x, tid = threadIdx.x;    // 256 threads
    __shared__ float lg[VV];
    __shared__ float rbuf[256];

    float lmax = -1e30f;
    for (int v = tid; v < VV; v += 256) {
        float x = bc[v];
#pragma unroll
        for (int s = 0; s < 4; s++) x += g_parts[((size_t)s * G4 + v) * BB + b];
        lg[v] = x;
        lmax = fmaxf(lmax, x);
    }
    rbuf[tid] = lmax; __syncthreads();
    for (int o = 128; o > 0; o >>= 1) {
        if (tid < o) rbuf[tid] = fmaxf(rbuf[tid], rbuf[tid + o]);
        __syncthreads();
    }
    float mx = rbuf[0];
    __syncthreads();
    float ls = 0.f;
    for (int v = tid; v < VV; v += 256) ls += expf(lg[v] - mx);
    rbuf[tid] = ls; __syncthreads();
    for (int o = 128; o > 0; o >>= 1) {
        if (tid < o) rbuf[tid] += rbuf[tid + o];
        __syncthreads();
    }
    float lse = mx + logf(rbuf[0]);
    for (int v = tid; v < VV; v += 256) {
        float r = lg[v] - lse;
        preds_out[b * VV + v] = r;
        g_x[b * XD + v] = r;
    }
}

// ---------------------------------------------------------------------------
// Launcher: graph-capturable, deterministic, allocation-free.
// ---------------------------------------------------------------------------
extern "C" void kernel_launch(void* const* d_in, const int* in_sizes, int n_in,
                              void* d_out, int out_size) {
    const float* lis  = (const float*)d_in[0];
    const float* Wih0 = (const float*)d_in[1];
    const float* Whh0 = (const float*)d_in[2];
    const float* bih0 = (const float*)d_in[3];
    const float* bhh0 = (const float*)d_in[4];
    const float* Wih1 = (const float*)d_in[5];
    const float* Whh1 = (const float*)d_in[6];
    const float* bih1 = (const float*)d_in[7];
    const float* bhh1 = (const float*)d_in[8];
    const float* Wphi = (const float*)d_in[9];
    const float* bphi = (const float*)d_in[10];
    const float* Wpsi = (const float*)d_in[11];
    const float* bpsi = (const float*)d_in[12];
    const float* Wc   = (const float*)d_in[13];
    const float* bc   = (const float*)d_in[14];

    float* preds = (float*)d_out;                          // [100,32,2000]
    float* attns = preds + (size_t)NSTEP * BB * VV;        // [100,32,256]

    float *x, *h0, *c0, *h1, *c1, *cat, *parts;
    cudaGetSymbolAddress((void**)&x,     g_x);
    cudaGetSymbolAddress((void**)&h0,    g_h0);
    cudaGetSymbolAddress((void**)&c0,    g_c0);
    cudaGetSymbolAddress((void**)&h1,    g_h1);
    cudaGetSymbolAddress((void**)&c1,    g_c1);
    cudaGetSymbolAddress((void**)&cat,   g_cat);
    cudaGetSymbolAddress((void**)&parts, g_parts);

    // init state + x0
    k_init<<<(BB * XD + 255) / 256, 256>>>(lis);
    // time-invariant psi(listener), transposed
    k_psi<<<dim3(8, 4, BB), 128>>>(lis, Wpsi, bpsi);

    for (int t = 0; t < NSTEP; t++) {
        // LSTM layer 0: gates = x@Wih0^T + h0@Whh0^T  (K-split 6 + 2 slots)
        k_gemm<<<dim3(32, 8), 128>>>(Wih0, x, XD, 6, Whh0, h0, HH, G4, parts);
        k_cell<<<64, 256>>>(parts, 8, bih0, bhh0, h0, c0, nullptr);
        // LSTM layer 1: gates = h0@Wih1^T + h1@Whh1^T  (2 + 2 slots)
        k_gemm<<<dim3(32, 4), 128>>>(Wih1, h0, HH, 2, Whh1, h1, HH, G4, parts);
        k_cell<<<64, 256>>>(parts, 4, bih1, bhh1, h1, c1, cat);
        // phi: comp_dec partials (slots 0,1; rows 0..255)
        k_gemm<<<dim3(4, 2), 128>>>(Wphi, h1, HH, 2, Wphi, h1, HH, MM, parts);
        // attention: energy -> softmax -> context (+ attn output)
        k_attn<<<32, 256>>>(lis, bphi, attns + (size_t)t * BB * TL);
        // character distribution: logits partials (slots 0..3)
        k_gemm<<<dim3(32, 4), 128>>>(Wc, cat, CATD, 4, Wc, cat, CATD, VV, parts);
        // log-softmax + feedback (+ preds output)
        k_logsm<<<32, 256>>>(bc, preds + (size_t)t * BB * VV);
    }
}